// round 1
// baseline (speedup 1.0000x reference)
#include <cuda_runtime.h>
#include <math.h>

#define BB 2
#define CC 64
#define NN 16384
#define DD 3
#define KK 128
#define EE 262144
#define FD 576   // 128 cos + 128 sin + 64 x + 192 gradf + 64 h

// ---------------- scratch (static device globals; no runtime alloc) ----------------
__device__ float d_feat[BB * FD * NN];        // feature matrix (B, 576, N)
__device__ float d_xT[BB * NN * CC];          // x transposed (B, N, C)
__device__ float d_gradf[BB * NN * 192];      // scatter result (B, N, 192)
__device__ float d_xc[BB * CC * KK];
__device__ float d_xs[BB * CC * KK];
__device__ float d_x0[BB * CC];
__device__ float d_Wcat[BB * CC * FD];        // fused left matrix (B, 64, 576)
__device__ float d_bias[BB * CC];             // f_0
__device__ float d_T[BB * CC * NN];           // wx @ x
__device__ float d_wcT[KK * CC * CC];         // weights_c transposed to (k,i,o)
__device__ float d_wsT[KK * CC * CC];
__device__ int   d_cnt[BB * NN];
__device__ int   d_off[BB * (NN + 1)];
__device__ int   d_cur[BB * NN];
__device__ int   d_perm[BB * EE];

// ---------------- zero accumulators ----------------
__global__ void k_zero() {
    int i = blockIdx.x * blockDim.x + threadIdx.x;
    if (i < BB * NN) d_cnt[i] = 0;
    if (i < BB * CC * KK) { d_xc[i] = 0.f; d_xs[i] = 0.f; }
    if (i < BB * CC) d_x0[i] = 0.f;
}

// ---------------- bases: cos/sin(nodes . modes) -> feat rows [0,256) ----------------
__global__ void k_bases(const float* __restrict__ nodes, const float* __restrict__ modes) {
    int n = blockIdx.x * blockDim.x + threadIdx.x;
    int k = blockIdx.y, b = blockIdx.z;
    float p0 = nodes[(b * NN + n) * 3 + 0];
    float p1 = nodes[(b * NN + n) * 3 + 1];
    float p2 = nodes[(b * NN + n) * 3 + 2];
    float t = p0 * modes[k * 3 + 0] + p1 * modes[k * 3 + 1] + p2 * modes[k * 3 + 2];
    float s, c;
    __sincosf(t, &s, &c);
    d_feat[(b * FD + k) * NN + n] = c;
    d_feat[(b * FD + KK + k) * NN + n] = s;
}

// ---------------- copy x -> feat rows [256,320) ----------------
__global__ void k_copyx(const float* __restrict__ x) {
    int i = blockIdx.x * 256 + threadIdx.x;   // over BB*CC*NN, layout matches
    int n = i & (NN - 1);
    int c = (i >> 14) & 63;
    int b = i >> 20;
    d_feat[(b * FD + 256 + c) * NN + n] = x[i];
}

// ---------------- transpose x -> xT (B,N,C) for edge gathers ----------------
__global__ void k_xT(const float* __restrict__ x) {
    __shared__ float tile[32][33];
    int b = blockIdx.z;
    int n0 = blockIdx.x * 32, c0 = blockIdx.y * 32;
    int tx = threadIdx.x, ty = threadIdx.y;   // (32, 8)
    for (int j = 0; j < 32; j += 8)
        tile[ty + j][tx] = x[(b * CC + c0 + ty + j) * NN + n0 + tx];
    __syncthreads();
    for (int j = 0; j < 32; j += 8)
        d_xT[(b * NN + n0 + ty + j) * CC + c0 + tx] = tile[tx][ty + j];
}

// ---------------- GEMM1: x_c[i,k]=sum_n x*nw*cos, x_s=-sum x*nw*sin, x_0=sum x*nw ----
__global__ __launch_bounds__(256) void k_gemm1(const float* __restrict__ x,
                                               const float* __restrict__ nwp) {
    const int b = blockIdx.y;
    const int nbase = blockIdx.x * 128;   // 128 chunks of 128 n
    __shared__ float sx[CC][33];
    __shared__ float sc[KK][33];
    __shared__ float ss[KK][33];
    int t = threadIdx.x;
    int ti = t & 15, tk = t >> 4;
    float aC[4][8] = {}, aS[4][8] = {}, a0[4] = {};
    for (int sub = 0; sub < 4; ++sub) {
        int n0 = nbase + sub * 32;
        #pragma unroll
        for (int j = 0; j < 8; ++j) {
            int e = t + j * 256; int r = e >> 5, col = e & 31;
            sx[r][col] = x[(b * CC + r) * NN + n0 + col] * nwp[b * NN + n0 + col];
        }
        #pragma unroll
        for (int j = 0; j < 16; ++j) {
            int e = t + j * 256; int r = e >> 5, col = e & 31;
            sc[r][col] = d_feat[(b * FD + r) * NN + n0 + col];
            ss[r][col] = d_feat[(b * FD + KK + r) * NN + n0 + col];
        }
        __syncthreads();
        for (int nn = 0; nn < 32; ++nn) {
            float xv[4];
            #pragma unroll
            for (int q = 0; q < 4; ++q) xv[q] = sx[ti + 16 * q][nn];
            if (tk == 0) {
                #pragma unroll
                for (int q = 0; q < 4; ++q) a0[q] += xv[q];
            }
            #pragma unroll
            for (int j = 0; j < 8; ++j) {
                float cv = sc[tk * 8 + j][nn];
                float sv = ss[tk * 8 + j][nn];
                #pragma unroll
                for (int q = 0; q < 4; ++q) {
                    aC[q][j] += xv[q] * cv;
                    aS[q][j] += xv[q] * sv;
                }
            }
        }
        __syncthreads();
    }
    #pragma unroll
    for (int q = 0; q < 4; ++q)
        #pragma unroll
        for (int j = 0; j < 8; ++j) {
            int i = ti + 16 * q, k = tk * 8 + j;
            atomicAdd(&d_xc[(b * CC + i) * KK + k], aC[q][j]);
            atomicAdd(&d_xs[(b * CC + i) * KK + k], -aS[q][j]);   // x_s = -sum
        }
    if (tk == 0)
        #pragma unroll
        for (int q = 0; q < 4; ++q)
            atomicAdd(&d_x0[b * CC + ti + 16 * q], a0[q]);
}

// ---------------- transpose weights_c/s (i,o,k) -> (k,i,o) ----------------
__global__ void k_wT(const float* __restrict__ wc, const float* __restrict__ ws) {
    int i = blockIdx.x * 256 + threadIdx.x;   // over KK*CC*CC
    int o = i & 63; int ii = (i >> 6) & 63; int k = i >> 12;
    d_wcT[i] = wc[(ii * 64 + o) * KK + k];
    d_wsT[i] = ws[(ii * 64 + o) * KK + k];
}

// ---------------- fourier mixing: f_c, f_s -> Wcat cols [0,256) ----------------
__global__ void k_fmix() {
    int k = blockIdx.x, b = blockIdx.y, o = threadIdx.x;
    __shared__ float sxc[64], sxs[64];
    sxc[o] = d_xc[(b * CC + o) * KK + k];
    sxs[o] = d_xs[(b * CC + o) * KK + k];
    __syncthreads();
    float fc = 0.f, fs = 0.f;
    for (int i = 0; i < 64; ++i) {
        float wc = d_wcT[(k * 64 + i) * 64 + o];
        float ws = d_wsT[(k * 64 + i) * 64 + o];
        fc += sxc[i] * wc - sxs[i] * ws;
        fs += sxs[i] * wc + sxc[i] * ws;
    }
    d_Wcat[(b * CC + o) * FD + k] = 2.f * fc;
    d_Wcat[(b * CC + o) * FD + KK + k] = -2.f * fs;
}

// ---------------- Wcat static columns: W, gw, w2 ----------------
__global__ void k_wcat_static(const float* __restrict__ W, const float* __restrict__ gwM,
                              const float* __restrict__ w2) {
    int i = blockIdx.x * 256 + threadIdx.x;   // over BB*CC*320
    if (i >= BB * CC * 320) return;
    int j = i % 320; int o = (i / 320) % CC; int b = i / (320 * CC);
    float v; int col;
    if (j < 64)       { v = W[o * 64 + j];          col = 256 + j; }
    else if (j < 256) { v = gwM[o * 192 + (j - 64)]; col = 320 + (j - 64); }
    else              { v = w2[o * 64 + (j - 256)]; col = 512 + (j - 256); }
    d_Wcat[(b * CC + o) * FD + col] = v;
}

// ---------------- bias f_0 = x_0 @ weights_0 ----------------
__global__ void k_bias(const float* __restrict__ w0) {
    int b = blockIdx.x, o = threadIdx.x;
    __shared__ float s0[64];
    s0[o] = d_x0[b * CC + o];
    __syncthreads();
    float f = 0.f;
    for (int i = 0; i < 64; ++i) f += s0[i] * w0[i * 64 + o];
    d_bias[b * CC + o] = f;
}

// ---------------- edge CSR: count -> scan -> fill ----------------
__global__ void k_count(const int* __restrict__ edges) {
    int i = blockIdx.x * 256 + threadIdx.x;   // b*EE + e
    int tgt = edges[2 * i];
    int b = i / EE;
    atomicAdd(&d_cnt[b * NN + tgt], 1);
}

__global__ void k_scan() {
    int b = blockIdx.x; int t = threadIdx.x;  // 1024 threads
    __shared__ int sm[1024];
    int vals[16]; int run = 0;
    #pragma unroll
    for (int j = 0; j < 16; ++j) {
        int v = d_cnt[b * NN + t * 16 + j];
        vals[j] = run; run += v;
    }
    sm[t] = run; __syncthreads();
    for (int off = 1; off < 1024; off <<= 1) {
        int v = (t >= off) ? sm[t - off] : 0;
        __syncthreads();
        sm[t] += v;
        __syncthreads();
    }
    int prev = (t > 0) ? sm[t - 1] : 0;
    #pragma unroll
    for (int j = 0; j < 16; ++j) {
        int val = prev + vals[j];
        d_off[b * (NN + 1) + t * 16 + j] = val;
        d_cur[b * NN + t * 16 + j] = val;
    }
    if (t == 1023) d_off[b * (NN + 1) + NN] = sm[1023];
}

__global__ void k_fill(const int* __restrict__ edges) {
    int i = blockIdx.x * 256 + threadIdx.x;   // b*EE + e
    int b = i / EE; int e = i - b * EE;
    int tgt = edges[2 * i];
    int slot = atomicAdd(&d_cur[b * NN + tgt], 1);
    d_perm[b * EE + slot] = e;
}

// ---------------- gather: warp per node, register accumulation (no float atomics) ----
__global__ void k_gather(const int* __restrict__ edges, const float* __restrict__ egw) {
    int wid = (blockIdx.x * blockDim.x + threadIdx.x) >> 5;
    int lane = threadIdx.x & 31;
    if (wid >= BB * NN) return;
    int b = wid >> 14, n = wid & (NN - 1);
    const float* xb = &d_xT[b * NN * CC];
    float t0 = xb[n * CC + lane], t1 = xb[n * CC + lane + 32];
    float a0 = 0, a1 = 0, a2 = 0, a3 = 0, a4 = 0, a5 = 0;
    int s = d_off[b * (NN + 1) + n], e_ = d_off[b * (NN + 1) + n + 1];
    for (int p = s; p < e_; ++p) {
        int e = d_perm[b * EE + p];
        int src = edges[(b * EE + e) * 2 + 1];
        float dd0 = xb[src * CC + lane] - t0;
        float dd1 = xb[src * CC + lane + 32] - t1;
        float w0_ = egw[(b * EE + e) * 3 + 0];
        float w1_ = egw[(b * EE + e) * 3 + 1];
        float w2_ = egw[(b * EE + e) * 3 + 2];
        a0 += dd0 * w0_; a1 += dd0 * w1_; a2 += dd0 * w2_;
        a3 += dd1 * w0_; a4 += dd1 * w1_; a5 += dd1 * w2_;
    }
    float* g = &d_gradf[(b * NN + n) * 192];
    g[lane * 3 + 0] = a0; g[lane * 3 + 1] = a1; g[lane * 3 + 2] = a2;
    g[(lane + 32) * 3 + 0] = a3; g[(lane + 32) * 3 + 1] = a4; g[(lane + 32) * 3 + 2] = a5;
}

// ---------------- transpose gradf (N,192) -> feat rows [320,512) ----------------
__global__ void k_gT() {
    __shared__ float tile[32][33];
    int b = blockIdx.z;
    int n0 = blockIdx.x * 32, g0 = blockIdx.y * 32;
    int tx = threadIdx.x, ty = threadIdx.y;   // (32, 8)
    for (int j = 0; j < 32; j += 8)
        tile[ty + j][tx] = d_gradf[(b * NN + n0 + ty + j) * 192 + g0 + tx];
    __syncthreads();
    for (int j = 0; j < 32; j += 8)
        d_feat[(b * FD + 320 + g0 + ty + j) * NN + n0 + tx] = tile[tx][ty + j];
}

// ---------------- generic 64 x KD x N GEMM body ----------------
template <int KD, bool DOGELU>
__device__ __forceinline__ void gemm64_body(const float* __restrict__ A, int aStride,
                                            const float* __restrict__ Bm,
                                            const float* __restrict__ bias,
                                            float* __restrict__ outp) {
    __shared__ __align__(16) float As[16][65];
    __shared__ __align__(16) float Bs[16][132];
    int b = blockIdx.y;
    int n0 = blockIdx.x * 128;
    int t = threadIdx.x;
    int lane = t & 31, wq = t >> 5;
    int to = wq * 8;
    float acc[8][4] = {};
    const float* Ab = A + b * aStride;
    const float* Bb = Bm + b * KD * NN;
    for (int kt = 0; kt < KD / 16; ++kt) {
        #pragma unroll
        for (int j = 0; j < 4; ++j) {
            int e = t + j * 256; int o = e >> 4, kk = e & 15;
            As[kk][o] = Ab[o * KD + kt * 16 + kk];
        }
        #pragma unroll
        for (int j = 0; j < 8; ++j) {
            int e = t + j * 256; int kk = e >> 7, nn = e & 127;
            Bs[kk][nn] = Bb[(kt * 16 + kk) * NN + n0 + nn];
        }
        __syncthreads();
        #pragma unroll
        for (int kk = 0; kk < 16; ++kk) {
            float4 bv = *reinterpret_cast<const float4*>(&Bs[kk][4 * lane]);
            #pragma unroll
            for (int r = 0; r < 8; ++r) {
                float av = As[kk][to + r];
                acc[r][0] += av * bv.x; acc[r][1] += av * bv.y;
                acc[r][2] += av * bv.z; acc[r][3] += av * bv.w;
            }
        }
        __syncthreads();
    }
    #pragma unroll
    for (int r = 0; r < 8; ++r) {
        int o = to + r;
        float bs = DOGELU ? bias[b * CC + o] : 0.f;
        float4 v;
        float* vp = &v.x;
        #pragma unroll
        for (int j = 0; j < 4; ++j) {
            float u = acc[r][j] + bs;
            if (DOGELU) u = 0.5f * u * (1.f + erff(u * 0.70710678118654752f));
            vp[j] = u;
        }
        *reinterpret_cast<float4*>(&outp[(b * CC + o) * NN + n0 + 4 * lane]) = v;
    }
}

__global__ __launch_bounds__(256) void k_gemm_T(const float* __restrict__ wx,
                                                const float* __restrict__ x) {
    gemm64_body<64, false>(wx, 0, x, nullptr, d_T);
}

__global__ __launch_bounds__(256) void k_gemm_final(float* __restrict__ outp) {
    gemm64_body<576, true>(d_Wcat, CC * FD, d_feat, d_bias, outp);
}

// ---------------- h = softsign(geo_wx @ geo) * (wx @ x) -> feat rows [512,576) ------
__global__ void k_h(const float* __restrict__ geo, const float* __restrict__ geo_wx) {
    int i = blockIdx.x * 256 + threadIdx.x;   // BB*CC*NN
    int n = i & (NN - 1); int o = (i >> 14) & 63; int b = i >> 20;
    float g = geo_wx[o * 3 + 0] * geo[(b * 3 + 0) * NN + n]
            + geo_wx[o * 3 + 1] * geo[(b * 3 + 1) * NN + n]
            + geo_wx[o * 3 + 2] * geo[(b * 3 + 2) * NN + n];
    float ssg = g / (1.f + fabsf(g));
    d_feat[(b * FD + 512 + o) * NN + n] = ssg * d_T[i];
}

// ---------------- launch ----------------
extern "C" void kernel_launch(void* const* d_in, const int* in_sizes, int n_in,
                              void* d_out, int out_size) {
    const float* x      = (const float*)d_in[0];
    const float* nodes  = (const float*)d_in[1];
    const float* nw     = (const float*)d_in[2];
    const float* geo    = (const float*)d_in[3];
    const int*   edges  = (const int*)d_in[4];
    const float* egw    = (const float*)d_in[5];
    const float* modes  = (const float*)d_in[6];
    const float* wc     = (const float*)d_in[7];
    const float* ws     = (const float*)d_in[8];
    const float* w0     = (const float*)d_in[9];
    const float* W      = (const float*)d_in[10];
    const float* gwM    = (const float*)d_in[11];
    const float* geo_wx = (const float*)d_in[12];
    const float* wx     = (const float*)d_in[13];
    const float* w2     = (const float*)d_in[14];
    float* outp = (float*)d_out;

    k_zero<<<(BB * NN + 255) / 256, 256>>>();
    k_bases<<<dim3(NN / 256, KK, BB), 256>>>(nodes, modes);
    k_copyx<<<BB * CC * NN / 256, 256>>>(x);
    k_xT<<<dim3(NN / 32, CC / 32, BB), dim3(32, 8)>>>(x);
    k_gemm1<<<dim3(128, BB), 256>>>(x, nw);
    k_wT<<<KK * CC * CC / 256, 256>>>(wc, ws);
    k_fmix<<<dim3(KK, BB), 64>>>();
    k_wcat_static<<<(BB * CC * 320 + 255) / 256, 256>>>(W, gwM, w2);
    k_bias<<<BB, 64>>>(w0);
    k_count<<<BB * EE / 256, 256>>>(edges);
    k_scan<<<BB, 1024>>>();
    k_fill<<<BB * EE / 256, 256>>>(edges);
    k_gather<<<BB * NN * 32 / 256, 256>>>(edges, egw);
    k_gT<<<dim3(NN / 32, 192 / 32, BB), dim3(32, 8)>>>();
    k_gemm_T<<<dim3(NN / 128, BB), 256>>>(wx, x);
    k_h<<<BB * CC * NN / 256, 256>>>(geo, geo_wx);
    k_gemm_final<<<dim3(NN / 128, BB), 256>>>(outp);
}